// round 12
// baseline (speedup 1.0000x reference)
#include <cuda_runtime.h>
#include <cuda_bf16.h>
#include <math.h>

// ---------------------------------------------------------------------------
// BCEDecorrelatedLoss, 2 kernels, NO big intermediate:
//   pair_kernel: O(N^2) packed-f32x2 pass; each block atomicAdds its partial
//                row sums {ra, rb, rab} straight into g_racc[i] (96KB, L2).
//   finalize_kernel: ONE block; computes 12 moments (fp32 per-thread over 8
//                rows, fp64 block combine), writes outputs, re-zeroes g_racc
//                for the next graph replay (globals start zeroed).
// ---------------------------------------------------------------------------

#define BLK      128
#define IPT      4            // i's per thread (2 packed f32x2 groups)
#define NPACK    (IPT/2)
#define ITILE    (BLK*IPT)    // 512
#define JCH      256          // j's per pair block
#define MAXN     8192
#define MAXSPLIT (MAXN/JCH)   // 32
#define FBLK     1024

typedef unsigned long long ull;
#define ABSM 0x7fffffff7fffffffULL

#define ADD2(d, a, b) asm("add.rn.f32x2 %0, %1, %2;" : "=l"(d) : "l"(a), "l"(b))
#define MUL2(d, a, b) asm("mul.rn.f32x2 %0, %1, %2;" : "=l"(d) : "l"(a), "l"(b))
#define FMA2(d, a, b, c) asm("fma.rn.f32x2 %0, %1, %2, %3;" : "=l"(d) : "l"(a), "l"(b), "l"(c))
#define PACK2(d, lo, hi) asm("mov.b64 %0, {%1, %2};" : "=l"(d) : "f"(lo), "f"(hi))

__device__ float4 g_racc[MAXN];   // {ra, rb, rab, pad}; zeroed by finalize

__global__ __launch_bounds__(BLK)
void pair_kernel(const float* __restrict__ x, const float* __restrict__ e,
                 const float* __restrict__ w, int n)
{
    // j-tile: {-x,-x,-e,-e} float4 (LDS.128) + {w,w} float2 (LDS.64)
    __shared__ float4 sxe[JCH];
    __shared__ float2 swd[JCH];
    const int js = blockIdx.y;
    const int j0 = js * JCH;
    const int t  = threadIdx.x;

#pragma unroll
    for (int jj = t; jj < JCH; jj += BLK) {
        int j = j0 + jj;
        bool ok = (j < n);
        float xv = ok ? x[j] : 0.0f;
        float ev = ok ? e[j] : 0.0f;
        float wv = ok ? w[j] : 0.0f;
        sxe[jj] = make_float4(-xv, -xv, -ev, -ev);
        swd[jj] = make_float2(wv, wv);
    }
    __syncthreads();

    const int ibase = blockIdx.x * ITILE + t;
    ull xi2[NPACK], ei2[NPACK];
    ull accA[NPACK], accB[NPACK], accAB[NPACK];
#pragma unroll
    for (int g = 0; g < NPACK; g++) {
        int ilo = ibase + (2 * g) * BLK;
        int ihi = ibase + (2 * g + 1) * BLK;
        float xlo = (ilo < n) ? x[ilo] : 0.0f;
        float xhi = (ihi < n) ? x[ihi] : 0.0f;
        float elo = (ilo < n) ? e[ilo] : 0.0f;
        float ehi = (ihi < n) ? e[ihi] : 0.0f;
        PACK2(xi2[g], xlo, xhi);
        PACK2(ei2[g], elo, ehi);
        accA[g] = 0ULL; accB[g] = 0ULL; accAB[g] = 0ULL;
    }

    const ull* pwd = (const ull*)swd;
#pragma unroll 8
    for (int k = 0; k < JCH; k++) {
        const float4 xe = sxe[k];            // LDS.128 broadcast
        const ull nxj = ((const ull*)&xe)[0];
        const ull nej = ((const ull*)&xe)[1];
        const ull wj  = pwd[k];              // LDS.64 broadcast
#pragma unroll
        for (int g = 0; g < NPACK; g++) {
            ull dx, de, awj;
            ADD2(dx, xi2[g], nxj);     // packed fma pipe
            ADD2(de, ei2[g], nej);
            dx &= ABSM;                // LOP3 -> alu pipe
            de &= ABSM;
            MUL2(awj, dx, wj);                  // |dx|*wj
            ADD2(accA[g], accA[g], awj);        // accA += |dx|*wj
            FMA2(accAB[g], awj, de, accAB[g]);  // accAB += |dx|*wj*|de|
            FMA2(accB[g], de, wj, accB[g]);     // accB += |de|*wj
        }
    }

    // accumulate straight into the 96KB row-sum array (spread-address REDG)
#pragma unroll
    for (int g = 0; g < NPACK; g++) {
        int ilo = ibase + (2 * g) * BLK;
        int ihi = ibase + (2 * g + 1) * BLK;
        float2 a = *(float2*)&accA[g];
        float2 b = *(float2*)&accB[g];
        float2 c = *(float2*)&accAB[g];
        if (ilo < n) {
            atomicAdd(&g_racc[ilo].x, a.x);
            atomicAdd(&g_racc[ilo].y, b.x);
            atomicAdd(&g_racc[ilo].z, c.x);
        }
        if (ihi < n) {
            atomicAdd(&g_racc[ihi].x, a.y);
            atomicAdd(&g_racc[ihi].y, b.y);
            atomicAdd(&g_racc[ihi].z, c.y);
        }
    }
}

// Single block: per-thread fp32 moments over 8 strided rows, fp64 combine,
// outputs, then re-zero g_racc for the next replay.
__global__ __launch_bounds__(FBLK)
void finalize_kernel(const float* __restrict__ x, const float* __restrict__ y,
                     const float* __restrict__ e, const float* __restrict__ w,
                     float* __restrict__ out, int n)
{
    __shared__ double sm[12][FBLK/32];
    const int tid  = threadIdx.x;
    const int lane = tid & 31;
    const int wid  = tid >> 5;

    float s[12];
#pragma unroll
    for (int k = 0; k < 12; k++) s[k] = 0.0f;

    for (int i = tid; i < n; i += FBLK) {
        float4 r  = g_racc[i];
        float ra  = r.x, rb = r.y, rab = r.z;
        float vi = w[i];
        float xi = x[i];
        float ei = e[i];
        float yi = y[i];
        float sp  = fmaxf(xi, 0.0f) + log1pf(expf(-fabsf(xi)));
        float bce = (sp - xi * yi) * vi;

        s[0]  += vi;
        s[1]  += vi * ra;
        s[2]  += vi * rb;
        s[3]  += vi * rab;
        s[4]  += vi * ra * rb;
        s[5]  += vi * ra * ra;
        s[6]  += vi * rb * rb;
        s[7]  += vi * xi;
        s[8]  += vi * xi * xi;
        s[9]  += vi * ei;
        s[10] += vi * ei * ei;
        s[11] += bce;
    }

    // fp64 warp reduce + cross-warp combine
#pragma unroll
    for (int k = 0; k < 12; k++) {
        double v = (double)s[k];
        for (int o = 16; o > 0; o >>= 1)
            v += __shfl_down_sync(0xffffffffu, v, o);
        if (lane == 0) sm[k][wid] = v;
    }
    __syncthreads();

    // consumption of g_racc is complete for all threads -> safe to re-zero
    for (int i = tid; i < MAXN; i += FBLK)
        g_racc[i] = make_float4(0.f, 0.f, 0.f, 0.f);

    if (wid == 0) {
        double t2[12];
#pragma unroll
        for (int k = 0; k < 12; k++)
            t2[k] = (lane < FBLK/32) ? sm[k][lane] : 0.0;
#pragma unroll
        for (int k = 0; k < 12; k++) {
            double v = t2[k];
            for (int o = 16; o > 0; o >>= 1)
                v += __shfl_down_sync(0xffffffffu, v, o);
            t2[k] = v;
        }
        if (lane == 0) {
            double sw  = t2[0];
            double Ra  = t2[1],  Rb  = t2[2],  Rab = t2[3];
            double P   = t2[4],  Qa  = t2[5],  Qb  = t2[6];
            double Vx  = t2[7],  Vx2 = t2[8];
            double Ve  = t2[9],  Ve2 = t2[10];
            double Sbce = t2[11];

            double isw  = 1.0 / sw;
            double isw2 = isw * isw;
            double isw3 = isw2 * isw;
            double isw4 = isw2 * isw2;

            double num  = Rab * isw2 - 2.0 * P * isw3 + Ra * Rb * isw4;
            double dena = 2.0 * Vx2 * isw - 2.0 * Vx * Vx * isw2
                        - 2.0 * Qa * isw3 + Ra * Ra * isw4;
            double denb = 2.0 * Ve2 * isw - 2.0 * Ve * Ve * isw2
                        - 2.0 * Qb * isw3 + Rb * Rb * isw4;

            double disco = num / sqrt(dena * denb);
            double bce   = Sbce / (double)n;

            out[0] = (float)bce;
            out[1] = (float)disco;
            out[2] = (float)(bce + 0.1 * disco);
        }
    }
}

extern "C" void kernel_launch(void* const* d_in, const int* in_sizes, int n_in,
                              void* d_out, int out_size)
{
    const float* x = (const float*)d_in[0];   // outputs (logits)
    const float* y = (const float*)d_in[1];   // labels
    const float* e = (const float*)d_in[2];   // event
    const float* w = (const float*)d_in[3];   // weights
    float* out = (float*)d_out;
    const int n = in_sizes[0];

    int itiles = (n + ITILE - 1) / ITILE;     // 16 for n=8192
    int jsplit = (n + JCH - 1) / JCH;         // 32 for n=8192
    if (jsplit > MAXSPLIT) jsplit = MAXSPLIT;

    dim3 grid(itiles, jsplit);
    pair_kernel<<<grid, BLK>>>(x, e, w, n);
    finalize_kernel<<<1, FBLK>>>(x, y, e, w, out, n);
}